// round 7
// baseline (speedup 1.0000x reference)
#include <cuda_runtime.h>
#include <math.h>

#define BB 8
#define NN 4096
#define MM 4096
#define DD 128
#define QSCALE 25.0f
#define SMEM_TOTAL 32768      // 2 mats * 128 rows * 128B (int8, full K)

// ---------------- scratch ----------------
__device__ int g_rowmin[BB * NN];
__device__ int g_colmin[BB * MM];
__device__ int g_x2i[BB * NN];
__device__ int g_y2i[BB * MM];
__device__ unsigned char g_xq[(size_t)BB * NN * DD];
__device__ unsigned char g_yq[(size_t)BB * MM * DD];
__device__ float g_sum;
__device__ unsigned g_ticket;

// One warp per row: quantize to int8 (scale 25), exact integer norms, min-init.
__global__ void quant_kernel(const float* __restrict__ x, const float* __restrict__ y) {
    int gw   = (blockIdx.x * blockDim.x + threadIdx.x) >> 5;
    int lane = threadIdx.x & 31;
    const float* src;
    unsigned char* dstq;
    int* dstn;
    int* mins;
    int row;
    if (gw < BB * NN) { src = x; dstq = g_xq; dstn = g_x2i; mins = g_rowmin; row = gw; }
    else              { src = y; dstq = g_yq; dstn = g_y2i; mins = g_colmin; row = gw - BB * NN; }

    const float4* p = reinterpret_cast<const float4*>(src + (size_t)row * DD);
    float4 v = p[lane];
    int q0 = max(-127, min(127, __float2int_rn(v.x * QSCALE)));
    int q1 = max(-127, min(127, __float2int_rn(v.y * QSCALE)));
    int q2 = max(-127, min(127, __float2int_rn(v.z * QSCALE)));
    int q3 = max(-127, min(127, __float2int_rn(v.w * QSCALE)));

    unsigned pack = (unsigned)(q0 & 255) | ((unsigned)(q1 & 255) << 8) |
                    ((unsigned)(q2 & 255) << 16) | ((unsigned)(q3 & 255) << 24);
    *reinterpret_cast<unsigned*>(dstq + (size_t)row * DD + lane * 4) = pack;

    int s = q0 * q0 + q1 * q1 + q2 * q2 + q3 * q3;
    #pragma unroll
    for (int o = 16; o; o >>= 1) s += __shfl_xor_sync(0xFFFFFFFFu, s, o);
    if (lane == 0) {
        dstn[row] = s;
        mins[row] = 0x7FFFFFFF;
    }
    if (blockIdx.x == 0 && threadIdx.x == 0) {
        g_sum = 0.0f;
        g_ticket = 0;
    }
}

// ---------------- device helpers ----------------
__device__ __forceinline__ unsigned smem_u32(const void* p) {
    unsigned a;
    asm("{ .reg .u64 t; cvta.to.shared.u64 t, %1; cvt.u32.u64 %0, t; }" : "=r"(a) : "l"(p));
    return a;
}

__device__ __forceinline__ void mma_s8(int* c, const unsigned* a, unsigned b0, unsigned b1) {
    asm volatile(
        "mma.sync.aligned.m16n8k32.row.col.s32.s8.s8.s32 "
        "{%0,%1,%2,%3}, {%4,%5,%6,%7}, {%8,%9}, {%0,%1,%2,%3};"
        : "+r"(c[0]), "+r"(c[1]), "+r"(c[2]), "+r"(c[3])
        : "r"(a[0]), "r"(a[1]), "r"(a[2]), "r"(a[3]), "r"(b0), "r"(b1));
}

__device__ __forceinline__ void ldsm4(unsigned* r, unsigned addr) {
    asm volatile("ldmatrix.sync.aligned.m8n8.x4.shared.b16 {%0,%1,%2,%3}, [%4];"
                 : "=r"(r[0]), "=r"(r[1]), "=r"(r[2]), "=r"(r[3]) : "r"(addr));
}

#define CP_ASYNC16(dst, src) \
    asm volatile("cp.async.cg.shared.global [%0], [%1], 16;" :: "r"(dst), "l"(src))
#define CP_COMMIT() asm volatile("cp.async.commit_group;" ::: "memory")
#define CP_WAIT(n)  asm volatile("cp.async.wait_group %0;" :: "n"(n) : "memory")

// ---------------- main kernel ----------------
// 128x128 tile, 256 threads (8 warps 2x4), warp tile 64x32, int8 m16n8k32.
// Full K=128 int8 = 128B rows, one 16KB tile per matrix, SW128 swizzle
// byte_in_row ^= (row&7)<<4. Loads split into two half-K cp.async groups.
__global__ __launch_bounds__(256, 2)
void chamfer_imma_kernel() {
    extern __shared__ char smem[];
    const unsigned sbase = smem_u32(smem);

    const int t    = threadIdx.x;
    const int lane = t & 31;
    const int wid  = t >> 5;
    const int wi   = wid >> 2;    // 0..1 (64-row slab)
    const int wj   = wid & 3;     // 0..3 (32-col slab)
    const int g    = lane >> 2;   // 0..7
    const int tig  = lane & 3;    // 0..3

    const int b    = blockIdx.z;
    const int iblk = blockIdx.x * 128;
    const int jblk = blockIdx.y * 128;

    const unsigned char* xq = g_xq + ((size_t)b * NN + iblk) * DD;
    const unsigned char* yq = g_yq + ((size_t)b * MM + jblk) * DD;

    // ldmatrix constant per-thread address parts (same derivation as fp16; int8
    // m16n8k32 fragments map to identical per-lane row/half pattern).
    const unsigned swz = (unsigned)(lane & 7) << 4;
    const int arow_base = wi * 64 + (lane & 15);
    const int brow_base = wj * 32 + (lane & 7) + ((lane & 8) ? 8 : 0);
    const unsigned khalf = (lane & 16) ? 16u : 0u;

    int acc[4][4][4];
    #pragma unroll
    for (int mt = 0; mt < 4; mt++)
        #pragma unroll
        for (int nt = 0; nt < 4; nt++)
            #pragma unroll
            for (int r = 0; r < 4; r++) acc[mt][nt][r] = 0;

    // Prefetch half h (bytes h*64 .. h*64+63 of each 128B row), both matrices.
    // Per half: 2 mats * 128 rows * 4 x 16B = 1024 ops -> 4 per thread.
    #define PREFETCH_HALF(h)                                                           \
        do {                                                                            \
            _Pragma("unroll")                                                           \
            for (int mat = 0; mat < 2; mat++)                                           \
                _Pragma("unroll")                                                       \
                for (int pp = 0; pp < 2; pp++) {                                        \
                    int idx = pp * 256 + t;                                             \
                    int row = idx >> 2;                                                 \
                    int c4  = idx & 3;                                                  \
                    unsigned bytecol = (h) * 64 + c4 * 16;                              \
                    const unsigned char* gsrc = (mat ? yq : xq) + (size_t)row * DD + bytecol; \
                    unsigned d = sbase + mat * 16384 + row * 128 +                      \
                                 (bytecol ^ (((unsigned)(row & 7)) << 4));              \
                    CP_ASYNC16(d, gsrc);                                                \
                }                                                                       \
        } while (0)

    PREFETCH_HALF(0);
    CP_COMMIT();
    PREFETCH_HALF(1);
    CP_COMMIT();

    const unsigned abase = sbase;
    const unsigned bbase = sbase + 16384;

    #pragma unroll
    for (int half = 0; half < 2; half++) {
        if (half == 0) CP_WAIT(1); else CP_WAIT(0);
        __syncthreads();

        #pragma unroll
        for (int ki = 0; ki < 2; ki++) {          // two k32 steps per half
            const unsigned k0b = (half * 2 + ki) * 32;
            unsigned af[4][4], bq[2][4];
            #pragma unroll
            for (int mt = 0; mt < 4; mt++) {
                int row = arow_base + mt * 16;
                ldsm4(af[mt], abase + row * 128 + ((k0b + khalf) ^ swz));
            }
            #pragma unroll
            for (int pr = 0; pr < 2; pr++) {
                int row = brow_base + pr * 16;
                ldsm4(bq[pr], bbase + row * 128 + ((k0b + khalf) ^ swz));
            }
            #pragma unroll
            for (int mt = 0; mt < 4; mt++)
                #pragma unroll
                for (int nt = 0; nt < 4; nt++)
                    mma_s8(acc[mt][nt], af[mt],
                           bq[nt >> 1][nt & 1], bq[nt >> 1][(nt & 1) + 2]);
        }
    }

    // ---- epilogue: exact integer d2 = x2 + y2 - 2*dot, int mins ----
    int x2v[4][2], y2v[4][2];
    #pragma unroll
    for (int mt = 0; mt < 4; mt++) {
        x2v[mt][0] = g_x2i[(size_t)b * NN + iblk + wi * 64 + mt * 16 + g];
        x2v[mt][1] = g_x2i[(size_t)b * NN + iblk + wi * 64 + mt * 16 + g + 8];
    }
    #pragma unroll
    for (int nt = 0; nt < 4; nt++) {
        y2v[nt][0] = g_y2i[(size_t)b * MM + jblk + wj * 32 + nt * 8 + 2 * tig];
        y2v[nt][1] = g_y2i[(size_t)b * MM + jblk + wj * 32 + nt * 8 + 2 * tig + 1];
    }

    int rmin[4][2], cmin[4][2];
    #pragma unroll
    for (int a_ = 0; a_ < 4; a_++) {
        rmin[a_][0] = rmin[a_][1] = 0x7FFFFFFF;
        cmin[a_][0] = cmin[a_][1] = 0x7FFFFFFF;
    }

    #pragma unroll
    for (int mt = 0; mt < 4; mt++)
        #pragma unroll
        for (int nt = 0; nt < 4; nt++)
            #pragma unroll
            for (int rr = 0; rr < 2; rr++)
                #pragma unroll
                for (int cc = 0; cc < 2; cc++) {
                    int d2 = x2v[mt][rr] + y2v[nt][cc] - 2 * acc[mt][nt][rr * 2 + cc];
                    rmin[mt][rr] = min(rmin[mt][rr], d2);
                    cmin[nt][cc] = min(cmin[nt][cc], d2);
                }

    #pragma unroll
    for (int mt = 0; mt < 4; mt++)
        #pragma unroll
        for (int rr = 0; rr < 2; rr++) {
            int v = rmin[mt][rr];
            v = min(v, __shfl_xor_sync(0xFFFFFFFFu, v, 1));
            v = min(v, __shfl_xor_sync(0xFFFFFFFFu, v, 2));
            rmin[mt][rr] = v;
        }
    #pragma unroll
    for (int nt = 0; nt < 4; nt++)
        #pragma unroll
        for (int cc = 0; cc < 2; cc++) {
            int v = cmin[nt][cc];
            v = min(v, __shfl_xor_sync(0xFFFFFFFFu, v, 4));
            v = min(v, __shfl_xor_sync(0xFFFFFFFFu, v, 8));
            v = min(v, __shfl_xor_sync(0xFFFFFFFFu, v, 16));
            cmin[nt][cc] = v;
        }

    __syncthreads();   // tile reads done before reusing smem
    int* rowbuf = reinterpret_cast<int*>(smem);          // [128][4]
    int* colbuf = reinterpret_cast<int*>(smem) + 512;    // [128][2]
    if (tig == 0) {
        #pragma unroll
        for (int mt = 0; mt < 4; mt++)
            #pragma unroll
            for (int rr = 0; rr < 2; rr++)
                rowbuf[(wi * 64 + mt * 16 + g + rr * 8) * 4 + wj] = rmin[mt][rr];
    }
    if (g == 0) {
        #pragma unroll
        for (int nt = 0; nt < 4; nt++)
            #pragma unroll
            for (int cc = 0; cc < 2; cc++)
                colbuf[(wj * 32 + nt * 8 + 2 * tig + cc) * 2 + wi] = cmin[nt][cc];
    }
    __syncthreads();

    if (t < 128) {
        int m = min(min(rowbuf[t * 4 + 0], rowbuf[t * 4 + 1]),
                    min(rowbuf[t * 4 + 2], rowbuf[t * 4 + 3]));
        atomicMin(&g_rowmin[(size_t)b * NN + iblk + t], m);
    } else {
        int j = t - 128;
        int m = min(colbuf[j * 2 + 0], colbuf[j * 2 + 1]);
        atomicMin(&g_colmin[(size_t)b * MM + jblk + j], m);
    }
}

// ---------------- final reduction (single kernel, ticket finish) ----------------
__global__ void reduce_kernel(float* __restrict__ out) {
    __shared__ float smr[256];
    int tid = threadIdx.x;
    int i = blockIdx.x * 256 + tid;
    float s = sqrtf((float)g_rowmin[i]) + sqrtf((float)g_colmin[i]);
    smr[tid] = s;
    __syncthreads();
    for (int o = 128; o > 0; o >>= 1) {
        if (tid < o) smr[tid] += smr[tid + o];
        __syncthreads();
    }
    if (tid == 0) {
        atomicAdd(&g_sum, smr[0]);
        __threadfence();
        unsigned old = atomicAdd(&g_ticket, 1u);
        if (old == 127u) {
            out[0] = g_sum * (1.0f / (QSCALE * (float)(BB * NN)));
        }
    }
}

extern "C" void kernel_launch(void* const* d_in, const int* in_sizes, int n_in,
                              void* d_out, int out_size) {
    const float* x = (const float*)d_in[0];
    const float* y = (const float*)d_in[1];
    float* out = (float*)d_out;
    (void)in_sizes; (void)n_in; (void)out_size;

    int total_warps = 2 * BB * NN;
    quant_kernel<<<(total_warps * 32 + 255) / 256, 256>>>(x, y);

    dim3 grid(NN / 128, MM / 128, BB);
    chamfer_imma_kernel<<<grid, 256, SMEM_TOTAL>>>();

    reduce_kernel<<<128, 256>>>(out);
}

// round 8
// speedup vs baseline: 1.8731x; 1.8731x over previous
#include <cuda_runtime.h>
#include <cuda_fp16.h>
#include <math.h>

#define BB 8
#define NN 4096
#define MM 4096
#define DD 128
#define STAGE_BYTES 32768     // 2 mats * 128 rows * 128B (64 fp16 cols)
#define NSTAGE 2
#define SMEM_TOTAL (NSTAGE * STAGE_BYTES)

// ---------------- scratch ----------------
__device__ float g_rowmin[BB * NN];
__device__ float g_colmin[BB * MM];
__device__ float g_x2[BB * NN];
__device__ float g_y2[BB * MM];
__device__ float g_sum;
__device__ unsigned g_ticket;
__device__ __half g_xh[(size_t)BB * NN * DD];
__device__ __half g_yh[(size_t)BB * MM * DD];

// One warp per row: fp32 norms (exact), min-init, fp16 conversion, counter reset.
__global__ void norms_conv_kernel(const float* __restrict__ x, const float* __restrict__ y) {
    int gw   = (blockIdx.x * blockDim.x + threadIdx.x) >> 5;
    int lane = threadIdx.x & 31;
    const float* src;
    float* dst;
    float* mins;
    __half* dsth;
    int row;
    if (gw < BB * NN) { src = x; dst = g_x2; mins = g_rowmin; dsth = g_xh; row = gw; }
    else              { src = y; dst = g_y2; mins = g_colmin; dsth = g_yh; row = gw - BB * NN; }
    const float4* p = reinterpret_cast<const float4*>(src + (size_t)row * DD);
    float4 v = p[lane];
    float s = v.x * v.x + v.y * v.y + v.z * v.z + v.w * v.w;
    #pragma unroll
    for (int o = 16; o; o >>= 1) s += __shfl_xor_sync(0xFFFFFFFFu, s, o);

    __half2 h0 = __floats2half2_rn(v.x, v.y);
    __half2 h1 = __floats2half2_rn(v.z, v.w);
    uint2 u;
    u.x = *reinterpret_cast<unsigned*>(&h0);
    u.y = *reinterpret_cast<unsigned*>(&h1);
    *reinterpret_cast<uint2*>(dsth + (size_t)row * DD + lane * 4) = u;

    if (lane == 0) {
        dst[row]  = s;
        mins[row] = __int_as_float(0x7F800000);
    }
    if (blockIdx.x == 0 && threadIdx.x == 0) {
        g_sum = 0.0f;
        g_ticket = 0u;
    }
}

// ---------------- device helpers ----------------
__device__ __forceinline__ unsigned smem_u32(const void* p) {
    unsigned a;
    asm("{ .reg .u64 t; cvta.to.shared.u64 t, %1; cvt.u32.u64 %0, t; }" : "=r"(a) : "l"(p));
    return a;
}

__device__ __forceinline__ void mma_f16(float* c, const unsigned* a, unsigned b0, unsigned b1) {
    asm volatile(
        "mma.sync.aligned.m16n8k16.row.col.f32.f16.f16.f32 "
        "{%0,%1,%2,%3}, {%4,%5,%6,%7}, {%8,%9}, {%0,%1,%2,%3};"
        : "+f"(c[0]), "+f"(c[1]), "+f"(c[2]), "+f"(c[3])
        : "r"(a[0]), "r"(a[1]), "r"(a[2]), "r"(a[3]), "r"(b0), "r"(b1));
}

__device__ __forceinline__ void ldsm4(unsigned* r, unsigned addr) {
    asm volatile("ldmatrix.sync.aligned.m8n8.x4.shared.b16 {%0,%1,%2,%3}, [%4];"
                 : "=r"(r[0]), "=r"(r[1]), "=r"(r[2]), "=r"(r[3]) : "r"(addr));
}

#define CP_ASYNC16(dst, src) \
    asm volatile("cp.async.cg.shared.global [%0], [%1], 16;" :: "r"(dst), "l"(src))
#define CP_COMMIT() asm volatile("cp.async.commit_group;" ::: "memory")
#define CP_WAIT(n)  asm volatile("cp.async.wait_group %0;" :: "n"(n) : "memory")

// ---------------- main kernel ----------------
// 128x128 block tile, 128 threads, 4 warps in 2x2 grid, warp tile 64x64.
// fp16 m16n8k16; K=128 as 2 chunks of 64 (128B rows), SW128 swizzle
// byte_in_row ^= (row&7)<<4.
__global__ __launch_bounds__(128, 2)
void chamfer_mma_kernel() {
    extern __shared__ char smem[];
    const unsigned sbase = smem_u32(smem);

    const int t    = threadIdx.x;
    const int lane = t & 31;
    const int wid  = t >> 5;
    const int wi   = wid >> 1;    // 0..1 (64-row slab)
    const int wj   = wid & 1;     // 0..1 (64-col slab)
    const int g    = lane >> 2;   // 0..7
    const int tig  = lane & 3;    // 0..3

    const int b    = blockIdx.z;
    const int iblk = blockIdx.x * 128;
    const int jblk = blockIdx.y * 128;

    const __half* xph = g_xh + ((size_t)b * NN + iblk) * DD;
    const __half* yph = g_yh + ((size_t)b * MM + jblk) * DD;

    const unsigned swz = (unsigned)(lane & 7) << 4;
    const int arow_base = wi * 64 + (lane & 15);                        // A m16 rows
    const int brow_base = wj * 64 + (lane & 7) + ((lane & 8) ? 8 : 0);  // B n16 rows
    const unsigned khalf = (lane & 16) ? 16u : 0u;

    float acc[4][8][4];
    #pragma unroll
    for (int mt = 0; mt < 4; mt++)
        #pragma unroll
        for (int nt = 0; nt < 8; nt++)
            #pragma unroll
            for (int r = 0; r < 4; r++) acc[mt][nt][r] = 0.0f;

    // Per stage: 2 mats * 128 rows * 8 x 16B = 2048 chunks; 16 per thread.
    #define PREFETCH(stage, chunk)                                                     \
        do {                                                                            \
            unsigned sdst = sbase + (stage) * STAGE_BYTES;                              \
            _Pragma("unroll")                                                           \
            for (int p = 0; p < 16; p++) {                                              \
                int idx = p * 128 + t;                                                  \
                int mat = idx >> 10;                                                    \
                int row = (idx >> 3) & 127;                                             \
                int c4  = idx & 7;                                                      \
                const __half* gsrc = (mat ? yph : xph) + (size_t)row * DD + (chunk) * 64 + c4 * 8; \
                unsigned d = sdst + mat * 16384 + row * 128 +                           \
                             (((unsigned)(c4 * 16)) ^ (((unsigned)(row & 7)) << 4));    \
                CP_ASYNC16(d, gsrc);                                                    \
            }                                                                           \
        } while (0)

    PREFETCH(0, 0);
    CP_COMMIT();
    PREFETCH(1, 1);
    CP_COMMIT();

    #pragma unroll
    for (int c = 0; c < 2; c++) {
        if (c == 0) CP_WAIT(1); else CP_WAIT(0);
        __syncthreads();

        const unsigned abase = sbase + c * STAGE_BYTES;
        const unsigned bbase = abase + 16384;

        #pragma unroll
        for (int ks = 0; ks < 4; ks++) {
            const unsigned k0b = ks * 32;
            unsigned af[4][4], bq[4][4];
            #pragma unroll
            for (int mt = 0; mt < 4; mt++) {
                int row = arow_base + mt * 16;
                ldsm4(af[mt], abase + row * 128 + ((k0b + khalf) ^ swz));
            }
            #pragma unroll
            for (int pr = 0; pr < 4; pr++) {
                int row = brow_base + pr * 16;
                ldsm4(bq[pr], bbase + row * 128 + ((k0b + khalf) ^ swz));
            }
            #pragma unroll
            for (int mt = 0; mt < 4; mt++)
                #pragma unroll
                for (int nt = 0; nt < 8; nt++)
                    mma_f16(acc[mt][nt], af[mt],
                            bq[nt >> 1][nt & 1], bq[nt >> 1][(nt & 1) + 2]);
        }
    }

    // ---- epilogue ----
    float x2v[4][2], y2v[8][2];
    #pragma unroll
    for (int mt = 0; mt < 4; mt++) {
        x2v[mt][0] = g_x2[(size_t)b * NN + iblk + wi * 64 + mt * 16 + g];
        x2v[mt][1] = g_x2[(size_t)b * NN + iblk + wi * 64 + mt * 16 + g + 8];
    }
    #pragma unroll
    for (int nt = 0; nt < 8; nt++) {
        y2v[nt][0] = g_y2[(size_t)b * MM + jblk + wj * 64 + nt * 8 + 2 * tig];
        y2v[nt][1] = g_y2[(size_t)b * MM + jblk + wj * 64 + nt * 8 + 2 * tig + 1];
    }

    const float INF = __int_as_float(0x7F800000);
    float rmin[4][2], cmin[8][2];
    #pragma unroll
    for (int mt = 0; mt < 4; mt++) rmin[mt][0] = rmin[mt][1] = INF;
    #pragma unroll
    for (int nt = 0; nt < 8; nt++) cmin[nt][0] = cmin[nt][1] = INF;

    #pragma unroll
    for (int mt = 0; mt < 4; mt++)
        #pragma unroll
        for (int nt = 0; nt < 8; nt++)
            #pragma unroll
            for (int rr = 0; rr < 2; rr++)
                #pragma unroll
                for (int cc = 0; cc < 2; cc++) {
                    float d2 = fmaxf(x2v[mt][rr] + y2v[nt][cc] - 2.0f * acc[mt][nt][rr * 2 + cc], 0.0f);
                    rmin[mt][rr] = fminf(rmin[mt][rr], d2);
                    cmin[nt][cc] = fminf(cmin[nt][cc], d2);
                }

    #pragma unroll
    for (int mt = 0; mt < 4; mt++)
        #pragma unroll
        for (int rr = 0; rr < 2; rr++) {
            float v = rmin[mt][rr];
            v = fminf(v, __shfl_xor_sync(0xFFFFFFFFu, v, 1));
            v = fminf(v, __shfl_xor_sync(0xFFFFFFFFu, v, 2));
            rmin[mt][rr] = v;
        }
    #pragma unroll
    for (int nt = 0; nt < 8; nt++)
        #pragma unroll
        for (int cc = 0; cc < 2; cc++) {
            float v = cmin[nt][cc];
            v = fminf(v, __shfl_xor_sync(0xFFFFFFFFu, v, 4));
            v = fminf(v, __shfl_xor_sync(0xFFFFFFFFu, v, 8));
            v = fminf(v, __shfl_xor_sync(0xFFFFFFFFu, v, 16));
            cmin[nt][cc] = v;
        }

    // Partial buffers in stage-0 region: all warps passed the chunk-1 barrier, and
    // chunk-1 compute reads stage 1 only — no hazard writing here; barrier before read.
    float* rowbuf = reinterpret_cast<float*>(smem);          // [128][2]
    float* colbuf = reinterpret_cast<float*>(smem) + 256;    // [128][2]
    if (tig == 0) {
        #pragma unroll
        for (int mt = 0; mt < 4; mt++)
            #pragma unroll
            for (int rr = 0; rr < 2; rr++)
                rowbuf[(wi * 64 + mt * 16 + g + rr * 8) * 2 + wj] = rmin[mt][rr];
    }
    if (g == 0) {
        #pragma unroll
        for (int nt = 0; nt < 8; nt++)
            #pragma unroll
            for (int cc = 0; cc < 2; cc++)
                colbuf[(wj * 64 + nt * 8 + 2 * tig + cc) * 2 + wi] = cmin[nt][cc];
    }
    __syncthreads();

    {
        float mr = fminf(rowbuf[t * 2 + 0], rowbuf[t * 2 + 1]);
        atomicMin((int*)&g_rowmin[(size_t)b * NN + iblk + t], __float_as_int(mr));
        float mc = fminf(colbuf[t * 2 + 0], colbuf[t * 2 + 1]);
        atomicMin((int*)&g_colmin[(size_t)b * MM + jblk + t], __float_as_int(mc));
    }
}

// ---------------- fused final reduction (ticket finish) ----------------
__global__ void reduce_kernel(float* __restrict__ out) {
    __shared__ float smr[256];
    int tid = threadIdx.x;
    int i = blockIdx.x * 256 + tid;
    float s = sqrtf(g_rowmin[i]) + sqrtf(g_colmin[i]);
    smr[tid] = s;
    __syncthreads();
    for (int o = 128; o > 0; o >>= 1) {
        if (tid < o) smr[tid] += smr[tid + o];
        __syncthreads();
    }
    if (tid == 0) {
        atomicAdd(&g_sum, smr[0]);
        __threadfence();
        unsigned old = atomicAdd(&g_ticket, 1u);
        if (old == 127u) out[0] = g_sum / (float)(BB * NN);
    }
}

extern "C" void kernel_launch(void* const* d_in, const int* in_sizes, int n_in,
                              void* d_out, int out_size) {
    const float* x = (const float*)d_in[0];
    const float* y = (const float*)d_in[1];
    float* out = (float*)d_out;
    (void)in_sizes; (void)n_in; (void)out_size;

    cudaFuncSetAttribute(chamfer_mma_kernel, cudaFuncAttributeMaxDynamicSharedMemorySize, SMEM_TOTAL);

    int total_warps = 2 * BB * NN;
    norms_conv_kernel<<<(total_warps * 32 + 255) / 256, 256>>>(x, y);

    dim3 grid(NN / 128, MM / 128, BB);
    chamfer_mma_kernel<<<grid, 128, SMEM_TOTAL>>>();

    reduce_kernel<<<128, 256>>>(out);
}

// round 9
// speedup vs baseline: 1.8824x; 1.0049x over previous
#include <cuda_runtime.h>
#include <cuda_fp16.h>
#include <math.h>

#define BB 8
#define NN 4096
#define MM 4096
#define DD 128
#define STAGE_BYTES 32768     // 2 mats * 128 rows * 128B (64 fp16 cols)
#define NSTAGE 2
#define SMEM_TOTAL (NSTAGE * STAGE_BYTES)

// ---------------- scratch ----------------
__device__ float g_rowmin[BB * NN];
__device__ float g_colmin[BB * MM];
__device__ float g_x2[BB * NN];
__device__ float g_y2[BB * MM];
__device__ float g_sum;
__device__ unsigned g_ticket;
__device__ __half g_xh[(size_t)BB * NN * DD];
__device__ __half g_yh[(size_t)BB * MM * DD];

// One warp per row: fp32 norms (exact), min-init, fp16 conversion, counter reset.
__global__ void norms_conv_kernel(const float* __restrict__ x, const float* __restrict__ y) {
    int gw   = (blockIdx.x * blockDim.x + threadIdx.x) >> 5;
    int lane = threadIdx.x & 31;
    const float* src;
    float* dst;
    float* mins;
    __half* dsth;
    int row;
    if (gw < BB * NN) { src = x; dst = g_x2; mins = g_rowmin; dsth = g_xh; row = gw; }
    else              { src = y; dst = g_y2; mins = g_colmin; dsth = g_yh; row = gw - BB * NN; }
    const float4* p = reinterpret_cast<const float4*>(src + (size_t)row * DD);
    float4 v = p[lane];
    float s = v.x * v.x + v.y * v.y + v.z * v.z + v.w * v.w;
    #pragma unroll
    for (int o = 16; o; o >>= 1) s += __shfl_xor_sync(0xFFFFFFFFu, s, o);

    __half2 h0 = __floats2half2_rn(v.x, v.y);
    __half2 h1 = __floats2half2_rn(v.z, v.w);
    uint2 u;
    u.x = *reinterpret_cast<unsigned*>(&h0);
    u.y = *reinterpret_cast<unsigned*>(&h1);
    *reinterpret_cast<uint2*>(dsth + (size_t)row * DD + lane * 4) = u;

    if (lane == 0) {
        dst[row]  = s;
        mins[row] = __int_as_float(0x7F800000);
    }
    if (blockIdx.x == 0 && threadIdx.x == 0) {
        g_sum = 0.0f;
        g_ticket = 0u;
    }
}

// ---------------- device helpers ----------------
__device__ __forceinline__ unsigned smem_u32(const void* p) {
    unsigned a;
    asm("{ .reg .u64 t; cvta.to.shared.u64 t, %1; cvt.u32.u64 %0, t; }" : "=r"(a) : "l"(p));
    return a;
}

__device__ __forceinline__ void mma_f16(float* c, const unsigned* a, unsigned b0, unsigned b1) {
    asm volatile(
        "mma.sync.aligned.m16n8k16.row.col.f32.f16.f16.f32 "
        "{%0,%1,%2,%3}, {%4,%5,%6,%7}, {%8,%9}, {%0,%1,%2,%3};"
        : "+f"(c[0]), "+f"(c[1]), "+f"(c[2]), "+f"(c[3])
        : "r"(a[0]), "r"(a[1]), "r"(a[2]), "r"(a[3]), "r"(b0), "r"(b1));
}

__device__ __forceinline__ void ldsm4(unsigned* r, unsigned addr) {
    asm volatile("ldmatrix.sync.aligned.m8n8.x4.shared.b16 {%0,%1,%2,%3}, [%4];"
                 : "=r"(r[0]), "=r"(r[1]), "=r"(r[2]), "=r"(r[3]) : "r"(addr));
}

#define CP_ASYNC16(dst, src) \
    asm volatile("cp.async.cg.shared.global [%0], [%1], 16;" :: "r"(dst), "l"(src))
#define CP_COMMIT() asm volatile("cp.async.commit_group;" ::: "memory")
#define CP_WAIT(n)  asm volatile("cp.async.wait_group %0;" :: "n"(n) : "memory")

// ---------------- main kernel ----------------
// 128x128 block tile, 128 threads, 4 warps 2x2, warp tile 64x64, fp16 m16n8k16.
// K=128 as 2 chunks of 64 (128B rows), SW128 swizzle byte^=(row&7)<<4.
// Fragment double-buffering: LDSM for kstep+1 issues during kstep's MMA chain.
__global__ __launch_bounds__(128, 2)
void chamfer_mma_kernel() {
    extern __shared__ char smem[];
    const unsigned sbase = smem_u32(smem);

    const int t    = threadIdx.x;
    const int lane = t & 31;
    const int wid  = t >> 5;
    const int wi   = wid >> 1;    // 0..1 (64-row slab)
    const int wj   = wid & 1;     // 0..1 (64-col slab)
    const int g    = lane >> 2;   // 0..7
    const int tig  = lane & 3;    // 0..3

    const int b    = blockIdx.z;
    const int iblk = blockIdx.x * 128;
    const int jblk = blockIdx.y * 128;

    const __half* xph = g_xh + ((size_t)b * NN + iblk) * DD;
    const __half* yph = g_yh + ((size_t)b * MM + jblk) * DD;

    const unsigned swz = (unsigned)(lane & 7) << 4;
    const int arow_base = wi * 64 + (lane & 15);
    const int brow_base = wj * 64 + (lane & 7) + ((lane & 8) ? 8 : 0);
    const unsigned khalf = (lane & 16) ? 16u : 0u;

    float acc[4][8][4];
    #pragma unroll
    for (int mt = 0; mt < 4; mt++)
        #pragma unroll
        for (int nt = 0; nt < 8; nt++)
            #pragma unroll
            for (int r = 0; r < 4; r++) acc[mt][nt][r] = 0.0f;

    #define PREFETCH(stage, chunk)                                                     \
        do {                                                                            \
            unsigned sdst = sbase + (stage) * STAGE_BYTES;                              \
            _Pragma("unroll")                                                           \
            for (int p = 0; p < 16; p++) {                                              \
                int idx = p * 128 + t;                                                  \
                int mat = idx >> 10;                                                    \
                int row = (idx >> 3) & 127;                                             \
                int c4  = idx & 7;                                                      \
                const __half* gsrc = (mat ? yph : xph) + (size_t)row * DD + (chunk) * 64 + c4 * 8; \
                unsigned d = sdst + mat * 16384 + row * 128 +                           \
                             (((unsigned)(c4 * 16)) ^ (((unsigned)(row & 7)) << 4));    \
                CP_ASYNC16(d, gsrc);                                                    \
            }                                                                           \
        } while (0)

    PREFETCH(0, 0);
    CP_COMMIT();
    PREFETCH(1, 1);
    CP_COMMIT();

    unsigned af[2][4][4], bq[2][4][4];

    #pragma unroll
    for (int c = 0; c < 2; c++) {
        if (c == 0) CP_WAIT(1); else CP_WAIT(0);
        __syncthreads();

        const unsigned abase = sbase + c * STAGE_BYTES;
        const unsigned bbase = abase + 16384;

        // prime kstep 0 fragments
        #pragma unroll
        for (int mt = 0; mt < 4; mt++)
            ldsm4(af[0][mt], abase + (arow_base + mt * 16) * 128 + (khalf ^ swz));
        #pragma unroll
        for (int pr = 0; pr < 4; pr++)
            ldsm4(bq[0][pr], bbase + (brow_base + pr * 16) * 128 + (khalf ^ swz));

        #pragma unroll
        for (int ks = 0; ks < 4; ks++) {
            const int cur = ks & 1;
            const int nxt = cur ^ 1;
            if (ks < 3) {                       // issue next kstep's LDSM up front
                const unsigned k0b = (ks + 1) * 32;
                #pragma unroll
                for (int mt = 0; mt < 4; mt++)
                    ldsm4(af[nxt][mt], abase + (arow_base + mt * 16) * 128 + ((k0b + khalf) ^ swz));
                #pragma unroll
                for (int pr = 0; pr < 4; pr++)
                    ldsm4(bq[nxt][pr], bbase + (brow_base + pr * 16) * 128 + ((k0b + khalf) ^ swz));
            }
            #pragma unroll
            for (int mt = 0; mt < 4; mt++)
                #pragma unroll
                for (int nt = 0; nt < 8; nt++)
                    mma_f16(acc[mt][nt], af[cur][mt],
                            bq[cur][nt >> 1][nt & 1], bq[cur][nt >> 1][(nt & 1) + 2]);
        }
    }

    // ---- epilogue (verified R8) ----
    float x2v[4][2], y2v[8][2];
    #pragma unroll
    for (int mt = 0; mt < 4; mt++) {
        x2v[mt][0] = g_x2[(size_t)b * NN + iblk + wi * 64 + mt * 16 + g];
        x2v[mt][1] = g_x2[(size_t)b * NN + iblk + wi * 64 + mt * 16 + g + 8];
    }
    #pragma unroll
    for (int nt = 0; nt < 8; nt++) {
        y2v[nt][0] = g_y2[(size_t)b * MM + jblk + wj * 64 + nt * 8 + 2 * tig];
        y2v[nt][1] = g_y2[(size_t)b * MM + jblk + wj * 64 + nt * 8 + 2 * tig + 1];
    }

    const float INF = __int_as_float(0x7F800000);
    float rmin[4][2], cmin[8][2];
    #pragma unroll
    for (int mt = 0; mt < 4; mt++) rmin[mt][0] = rmin[mt][1] = INF;
    #pragma unroll
    for (int nt = 0; nt < 8; nt++) cmin[nt][0] = cmin[nt][1] = INF;

    #pragma unroll
    for (int mt = 0; mt < 4; mt++)
        #pragma unroll
        for (int nt = 0; nt < 8; nt++)
            #pragma unroll
            for (int rr = 0; rr < 2; rr++)
                #pragma unroll
                for (int cc = 0; cc < 2; cc++) {
                    float d2 = fmaxf(x2v[mt][rr] + y2v[nt][cc] - 2.0f * acc[mt][nt][rr * 2 + cc], 0.0f);
                    rmin[mt][rr] = fminf(rmin[mt][rr], d2);
                    cmin[nt][cc] = fminf(cmin[nt][cc], d2);
                }

    #pragma unroll
    for (int mt = 0; mt < 4; mt++)
        #pragma unroll
        for (int rr = 0; rr < 2; rr++) {
            float v = rmin[mt][rr];
            v = fminf(v, __shfl_xor_sync(0xFFFFFFFFu, v, 1));
            v = fminf(v, __shfl_xor_sync(0xFFFFFFFFu, v, 2));
            rmin[mt][rr] = v;
        }
    #pragma unroll
    for (int nt = 0; nt < 8; nt++)
        #pragma unroll
        for (int cc = 0; cc < 2; cc++) {
            float v = cmin[nt][cc];
            v = fminf(v, __shfl_xor_sync(0xFFFFFFFFu, v, 4));
            v = fminf(v, __shfl_xor_sync(0xFFFFFFFFu, v, 8));
            v = fminf(v, __shfl_xor_sync(0xFFFFFFFFu, v, 16));
            cmin[nt][cc] = v;
        }

    __syncthreads();   // all warps done reading tiles before smem reuse
    float* rowbuf = reinterpret_cast<float*>(smem);          // [128][2]
    float* colbuf = reinterpret_cast<float*>(smem) + 256;    // [128][2]
    if (tig == 0) {
        #pragma unroll
        for (int mt = 0; mt < 4; mt++)
            #pragma unroll
            for (int rr = 0; rr < 2; rr++)
                rowbuf[(wi * 64 + mt * 16 + g + rr * 8) * 2 + wj] = rmin[mt][rr];
    }
    if (g == 0) {
        #pragma unroll
        for (int nt = 0; nt < 8; nt++)
            #pragma unroll
            for (int cc = 0; cc < 2; cc++)
                colbuf[(wj * 64 + nt * 8 + 2 * tig + cc) * 2 + wi] = cmin[nt][cc];
    }
    __syncthreads();

    {
        float mr = fminf(rowbuf[t * 2 + 0], rowbuf[t * 2 + 1]);
        atomicMin((int*)&g_rowmin[(size_t)b * NN + iblk + t], __float_as_int(mr));
        float mc = fminf(colbuf[t * 2 + 0], colbuf[t * 2 + 1]);
        atomicMin((int*)&g_colmin[(size_t)b * MM + jblk + t], __float_as_int(mc));
    }
}

// ---------------- fused final reduction (ticket finish) ----------------
__global__ void reduce_kernel(float* __restrict__ out) {
    __shared__ float smr[256];
    int tid = threadIdx.x;
    int i = blockIdx.x * 256 + tid;
    float s = sqrtf(g_rowmin[i]) + sqrtf(g_colmin[i]);
    smr[tid] = s;
    __syncthreads();
    for (int o = 128; o > 0; o >>= 1) {
        if (tid < o) smr[tid] += smr[tid + o];
        __syncthreads();
    }
    if (tid == 0) {
        atomicAdd(&g_sum, smr[0]);
        __threadfence();
        unsigned old = atomicAdd(&g_ticket, 1u);
        if (old == 127u) out[0] = g_sum / (float)(BB * NN);
    }
}

extern "C" void kernel_launch(void* const* d_in, const int* in_sizes, int n_in,
                              void* d_out, int out_size) {
    const float* x = (const float*)d_in[0];
    const float* y = (const float*)d_in[1];
    float* out = (float*)d_out;
    (void)in_sizes; (void)n_in; (void)out_size;

    cudaFuncSetAttribute(chamfer_mma_kernel, cudaFuncAttributeMaxDynamicSharedMemorySize, SMEM_TOTAL);

    int total_warps = 2 * BB * NN;
    norms_conv_kernel<<<(total_warps * 32 + 255) / 256, 256>>>(x, y);

    dim3 grid(NN / 128, MM / 128, BB);
    chamfer_mma_kernel<<<grid, 128, SMEM_TOTAL>>>();

    reduce_kernel<<<128, 256>>>(out);
}